// round 1
// baseline (speedup 1.0000x reference)
#include <cuda_runtime.h>
#include <math.h>

#define NN 50000
#define NE 1600000
#define H 128
#define NG 50
#define NGR 128
#define TABN 8192
#define WMAX 9.6f

// -------- scratch (device globals: allocation-free) --------
__device__ float g_h[NN * H];     // node features
__device__ float g_hx[NN * H];    // h @ cf_w1  (also reused as t buffer)
__device__ float g_agg[NN * H];   // scatter accumulator (also reused [N,64] for head)
__device__ float g_w[NE];         // edge distances
__device__ float g_tab[TABN * H]; // Wf(w)*C(w) lookup table (per interaction)
__device__ float g_gsum[NGR];
__device__ float g_gcnt[NGR];

__device__ __forceinline__ float ssp(float x) {
    // jax.nn.softplus(x) - log(2), numerically stable
    return fmaxf(x, 0.0f) + log1pf(expf(-fabsf(x))) - 0.69314718055994531f;
}

// -------- edge geometry: w = |pos[src] - pos[dst] - shift| --------
__global__ void edge_w_kernel(const float* __restrict__ pos,
                              const float* __restrict__ shift,
                              const int* __restrict__ ei) {
    int e = blockIdx.x * blockDim.x + threadIdx.x;
    if (e >= NE) return;
    int s = ei[e], d = ei[NE + e];
    float dx = pos[s * 3 + 0] - pos[d * 3 + 0] - shift[e * 3 + 0];
    float dy = pos[s * 3 + 1] - pos[d * 3 + 1] - shift[e * 3 + 1];
    float dz = pos[s * 3 + 2] - pos[d * 3 + 2] - shift[e * 3 + 2];
    g_w[e] = sqrtf(dx * dx + dy * dy + dz * dz);
}

// -------- h = emb[z] --------
__global__ void embed_kernel(const float* __restrict__ emb, const int* __restrict__ z) {
    int i = blockIdx.x * blockDim.x + threadIdx.x;
    if (i >= NN * H) return;
    int n = i >> 7, c = i & 127;
    g_h[i] = emb[z[n] * H + c];
}

__global__ void zero_agg_kernel() {
    int i = blockIdx.x * blockDim.x + threadIdx.x;
    if (i < NN * H) g_agg[i] = 0.0f;
}

__global__ void zero_small_kernel() {
    int i = threadIdx.x;
    if (i < NGR) { g_gsum[i] = 0.0f; g_gcnt[i] = 0.0f; }
}

// -------- build Wf(w)*C(w) lookup table: 8 samples per block --------
__global__ void table_kernel(const float* __restrict__ w1, const float* __restrict__ b1,
                             const float* __restrict__ w2, const float* __restrict__ b2) {
    __shared__ float gs[8][NG];
    __shared__ float t1s[8][H];
    int s0 = blockIdx.x * 8;
    int j = threadIdx.x;
    const float step = WMAX / (float)(TABN - 1);
    const float spacing = 8.0f / 49.0f;              // linspace(0,8,50) spacing
    const float coeff = -0.5f / (spacing * spacing);

    for (int idx = j; idx < 8 * NG; idx += blockDim.x) {
        int m = idx / NG, k = idx - m * NG;
        float ws = (float)(s0 + m) * step;
        float dd = ws - (float)k * spacing;
        gs[m][k] = expf(coeff * dd * dd);
    }
    __syncthreads();

    float acc[8];
#pragma unroll
    for (int m = 0; m < 8; m++) acc[m] = 0.0f;
    for (int k = 0; k < NG; k++) {
        float wv = w1[k * H + j];
#pragma unroll
        for (int m = 0; m < 8; m++) acc[m] += wv * gs[m][k];
    }
    float bb = b1[j];
#pragma unroll
    for (int m = 0; m < 8; m++) t1s[m][j] = ssp(acc[m] + bb);
    __syncthreads();

#pragma unroll
    for (int m = 0; m < 8; m++) acc[m] = 0.0f;
    for (int k = 0; k < H; k++) {
        float wv = w2[k * H + j];
#pragma unroll
        for (int m = 0; m < 8; m++) acc[m] += wv * t1s[m][k];
    }
    float b2v = b2[j];
#pragma unroll
    for (int m = 0; m < 8; m++) {
        float ws = (float)(s0 + m) * step;
        float C = 0.5f * (cosf(ws * (3.14159265358979f / 8.0f)) + 1.0f);
        g_tab[(s0 + m) * H + j] = (acc[m] + b2v) * C;
    }
}

// -------- generic node GEMM: out = [ssp](in @ W + b) [+= residual] --------
// block = 128 threads (thread j = output column), 16 nodes per block.
__global__ void node_gemm_kernel(const float* __restrict__ in, const float* __restrict__ W,
                                 const float* __restrict__ bias, float* __restrict__ out,
                                 int kin, int kout, int act, int residual) {
    __shared__ float As[16 * H];
    int n0 = blockIdx.x * 16;
    for (int i = threadIdx.x; i < 16 * kin; i += blockDim.x)
        As[i] = in[n0 * kin + i];
    __syncthreads();
    int j = threadIdx.x;
    if (j < kout) {
        float acc[16];
#pragma unroll
        for (int m = 0; m < 16; m++) acc[m] = 0.0f;
        for (int k = 0; k < kin; k++) {
            float wv = W[k * kout + j];
#pragma unroll
            for (int m = 0; m < 16; m++) acc[m] += wv * As[m * kin + k];
        }
        float b = bias ? bias[j] : 0.0f;
#pragma unroll
        for (int m = 0; m < 16; m++) {
            float v = acc[m] + b;
            if (act) v = ssp(v);
            if (residual) out[(n0 + m) * kout + j] += v;
            else          out[(n0 + m) * kout + j] = v;
        }
    }
}

// -------- edge message + scatter: one warp per edge --------
__global__ void edge_msg_kernel(const int* __restrict__ ei) {
    int gw = (blockIdx.x * blockDim.x + threadIdx.x) >> 5;
    int lane = threadIdx.x & 31;
    if (gw >= NE) return;
    int e = gw;
    float w = g_w[e];
    if (w >= WMAX) return;  // Wf is exactly 0 (gaussians underflow, zero biases)
    float f = w * ((float)(TABN - 1) / WMAX);
    int i0 = (int)f;
    if (i0 > TABN - 2) i0 = TABN - 2;
    float fr = f - (float)i0;
    int s = ei[e], d = ei[NE + e];

    const float4* ta = (const float4*)(g_tab + i0 * H);
    const float4* tb = (const float4*)(g_tab + (i0 + 1) * H);
    const float4* hx = (const float4*)(g_hx + (size_t)s * H);
    float* ag = g_agg + (size_t)d * H;

    float4 a = ta[lane];
    float4 b = tb[lane];
    float4 hv = hx[lane];
    float m0 = hv.x * fmaf(fr, b.x - a.x, a.x);
    float m1 = hv.y * fmaf(fr, b.y - a.y, a.y);
    float m2 = hv.z * fmaf(fr, b.z - a.z, a.z);
    float m3 = hv.w * fmaf(fr, b.w - a.w, a.w);
    atomicAdd(ag + lane * 4 + 0, m0);
    atomicAdd(ag + lane * 4 + 1, m1);
    atomicAdd(ag + lane * 4 + 2, m2);
    atomicAdd(ag + lane * 4 + 3, m3);
}

// -------- head stage 2 + per-graph reduction: one warp per node --------
__global__ void head2_kernel(const float* __restrict__ w2, const float* __restrict__ b2,
                             const int* __restrict__ batch) {
    int n = (blockIdx.x * blockDim.x + threadIdx.x) >> 5;
    int lane = threadIdx.x & 31;
    if (n >= NN) return;
    float v = g_agg[n * 64 + lane] * w2[lane] + g_agg[n * 64 + 32 + lane] * w2[32 + lane];
#pragma unroll
    for (int o = 16; o > 0; o >>= 1) v += __shfl_down_sync(0xffffffffu, v, o);
    if (lane == 0) {
        int g = batch[n];
        atomicAdd(&g_gsum[g], v + b2[0]);
        atomicAdd(&g_gcnt[g], 1.0f);
    }
}

__global__ void finalize_kernel(float* __restrict__ out) {
    int g = threadIdx.x;
    if (g < NGR) out[g] = g_gsum[g] / fmaxf(g_gcnt[g], 1.0f);
}

extern "C" void kernel_launch(void* const* d_in, const int* in_sizes, int n_in,
                              void* d_out, int out_size) {
    const float* pos     = (const float*)d_in[0];
    const float* shift   = (const float*)d_in[1];
    const float* emb     = (const float*)d_in[2];
    const float* mlp_w1  = (const float*)d_in[3];
    const float* mlp_b1  = (const float*)d_in[4];
    const float* mlp_w2  = (const float*)d_in[5];
    const float* mlp_b2  = (const float*)d_in[6];
    const float* cf_w1   = (const float*)d_in[7];
    const float* cf_w2   = (const float*)d_in[8];
    const float* cf_b2   = (const float*)d_in[9];
    const float* lin_w   = (const float*)d_in[10];
    const float* lin_b   = (const float*)d_in[11];
    const float* head_w1 = (const float*)d_in[12];
    const float* head_b1 = (const float*)d_in[13];
    const float* head_w2 = (const float*)d_in[14];
    const float* head_b2 = (const float*)d_in[15];
    const int*   z       = (const int*)d_in[16];
    const int*   ei      = (const int*)d_in[17];
    const int*   batch   = (const int*)d_in[18];
    float* out = (float*)d_out;

    float *p_h, *p_hx, *p_agg;
    cudaGetSymbolAddress((void**)&p_h,   g_h);
    cudaGetSymbolAddress((void**)&p_hx,  g_hx);
    cudaGetSymbolAddress((void**)&p_agg, g_agg);

    edge_w_kernel<<<(NE + 255) / 256, 256>>>(pos, shift, ei);
    embed_kernel<<<(NN * H + 255) / 256, 256>>>(emb, z);
    zero_small_kernel<<<1, 128>>>();

    for (int i = 0; i < 3; i++) {
        table_kernel<<<TABN / 8, 128>>>(mlp_w1 + i * NG * H, mlp_b1 + i * H,
                                        mlp_w2 + i * H * H,  mlp_b2 + i * H);
        zero_agg_kernel<<<(NN * H + 255) / 256, 256>>>();
        // hx = h @ cf_w1[i]
        node_gemm_kernel<<<NN / 16, 128>>>(p_h, cf_w1 + i * H * H, nullptr, p_hx, H, H, 0, 0);
        // agg[dst] += hx[src] * Wf(w)*C(w)
        edge_msg_kernel<<<NE / 8, 256>>>(ei);
        // t = ssp(agg @ cf_w2 + b2)   (t stored in hx, which is free now)
        node_gemm_kernel<<<NN / 16, 128>>>(p_agg, cf_w2 + i * H * H, cf_b2 + i * H, p_hx, H, H, 1, 0);
        // h += t @ lin_w + lin_b
        node_gemm_kernel<<<NN / 16, 128>>>(p_hx, lin_w + i * H * H, lin_b + i * H, p_h, H, H, 0, 1);
    }

    // head: u = ssp(h @ head_w1 + b1)  -> g_agg reused as [N,64]
    node_gemm_kernel<<<NN / 16, 128>>>(p_h, head_w1, head_b1, p_agg, H, 64, 1, 0);
    head2_kernel<<<(NN * 32 + 255) / 256, 256>>>(head_w2, head_b2, batch);
    finalize_kernel<<<1, 128>>>(out);
}

// round 3
// speedup vs baseline: 1.5791x; 1.5791x over previous
#include <cuda_runtime.h>
#include <math.h>

#define NN 50000
#define NE 1600000
#define H 128
#define NG 50
#define NGR 128
#define TABN 8192
#define WMAX 9.6f
#define GM 64   // gemm M-tile
#define KC 32   // gemm K-chunk staged in smem

// -------- scratch (device globals: allocation-free) --------
__device__ float g_h[NN * H];     // node features
__device__ float g_hx[NN * H];    // h @ cf_w1 (also reused as t buffer)
__device__ float g_agg[NN * H];   // scatter accumulator (also reused [N,64] for head)
__device__ float g_w[NE];         // edge distances
__device__ float g_tab[TABN * H]; // Wf(w)*C(w) lookup table (per interaction)
__device__ float g_gsum[NGR];
__device__ float g_gcnt[NGR];

__device__ __forceinline__ float ssp(float x) {
    return fmaxf(x, 0.0f) + log1pf(expf(-fabsf(x))) - 0.69314718055994531f;
}

// -------- edge geometry --------
__global__ void edge_w_kernel(const float* __restrict__ pos,
                              const float* __restrict__ shift,
                              const int* __restrict__ ei) {
    int e = blockIdx.x * blockDim.x + threadIdx.x;
    if (e >= NE) return;
    int s = ei[e], d = ei[NE + e];
    float dx = pos[s * 3 + 0] - pos[d * 3 + 0] - shift[e * 3 + 0];
    float dy = pos[s * 3 + 1] - pos[d * 3 + 1] - shift[e * 3 + 1];
    float dz = pos[s * 3 + 2] - pos[d * 3 + 2] - shift[e * 3 + 2];
    g_w[e] = sqrtf(dx * dx + dy * dy + dz * dz);
}

// -------- h = emb[z] --------
__global__ void embed_kernel(const float* __restrict__ emb, const int* __restrict__ z) {
    int i = blockIdx.x * blockDim.x + threadIdx.x;
    if (i >= NN * H) return;
    int n = i >> 7, c = i & 127;
    g_h[i] = emb[z[n] * H + c];
}

__global__ void zero_agg_kernel() {
    int i = blockIdx.x * blockDim.x + threadIdx.x;
    if (i < NN * H) g_agg[i] = 0.0f;
}

__global__ void zero_small_kernel() {
    int i = threadIdx.x;
    if (i < NGR) { g_gsum[i] = 0.0f; g_gcnt[i] = 0.0f; }
}

// -------- build Wf(w)*C(w) lookup table: 8 samples per block --------
__global__ void table_kernel(const float* __restrict__ w1, const float* __restrict__ b1,
                             const float* __restrict__ w2, const float* __restrict__ b2) {
    __shared__ float gs[8][NG];
    __shared__ float t1s[8][H];
    int s0 = blockIdx.x * 8;
    int j = threadIdx.x;
    const float step = WMAX / (float)(TABN - 1);
    const float spacing = 8.0f / 49.0f;
    const float coeff = -0.5f / (spacing * spacing);

    for (int idx = j; idx < 8 * NG; idx += blockDim.x) {
        int m = idx / NG, k = idx - m * NG;
        float ws = (float)(s0 + m) * step;
        float dd = ws - (float)k * spacing;
        gs[m][k] = expf(coeff * dd * dd);
    }
    __syncthreads();

    float acc[8];
#pragma unroll
    for (int m = 0; m < 8; m++) acc[m] = 0.0f;
    for (int k = 0; k < NG; k++) {
        float wv = w1[k * H + j];
#pragma unroll
        for (int m = 0; m < 8; m++) acc[m] += wv * gs[m][k];
    }
    float bb = b1[j];
#pragma unroll
    for (int m = 0; m < 8; m++) t1s[m][j] = ssp(acc[m] + bb);
    __syncthreads();

#pragma unroll
    for (int m = 0; m < 8; m++) acc[m] = 0.0f;
    for (int k = 0; k < H; k++) {
        float wv = w2[k * H + j];
#pragma unroll
        for (int m = 0; m < 8; m++) acc[m] += wv * t1s[m][k];
    }
    float b2v = b2[j];
#pragma unroll
    for (int m = 0; m < 8; m++) {
        float ws = (float)(s0 + m) * step;
        float C = 0.5f * (cosf(ws * (3.14159265358979f / 8.0f)) + 1.0f);
        g_tab[(s0 + m) * H + j] = (acc[m] + b2v) * C;
    }
}

// -------- tiled node GEMM: out = [ssp](in @ W + b) [+= residual] --------
// block 256 threads, tile 64 nodes x 128 cols. A resident in smem (32KB),
// W streamed through smem in 32-row chunks (16KB). 48KB static smem total.
// thread (cx = tid&31, mg = tid>>5) computes 8 rows x 4 cols.
__global__ __launch_bounds__(256) void gemm128_kernel(
    const float* __restrict__ in, const float* __restrict__ W,
    const float* __restrict__ bias, float* __restrict__ out,
    int act, int residual) {
    __shared__ float As[GM * H];   // 32 KB
    __shared__ float Ws[KC * H];   // 16 KB
    int n0 = blockIdx.x * GM;
    int tid = threadIdx.x;

    // stage A: 2048 float4 (bounds-checked)
    float4* As4 = (float4*)As;
    for (int i = tid; i < GM * H / 4; i += 256) {
        int m = i >> 5;
        float4 v = make_float4(0.f, 0.f, 0.f, 0.f);
        if (n0 + m < NN) v = ((const float4*)(in + (size_t)(n0 + m) * H))[i & 31];
        As4[i] = v;
    }

    int cx = tid & 31;
    int mg = tid >> 5;
    float acc[8][4];
#pragma unroll
    for (int r = 0; r < 8; r++)
#pragma unroll
        for (int c = 0; c < 4; c++) acc[r][c] = 0.0f;

    for (int kc = 0; kc < H; kc += KC) {
        __syncthreads();
        // stage W chunk: rows [kc, kc+KC) = 1024 float4
        const float4* Wc4 = (const float4*)(W + kc * H);
        float4* Ws4 = (float4*)Ws;
#pragma unroll
        for (int i = 0; i < KC * H / 4 / 256; i++)
            Ws4[tid + i * 256] = Wc4[tid + i * 256];
        __syncthreads();

#pragma unroll
        for (int k = 0; k < KC; k += 4) {
            float4 b0 = ((float4*)(Ws + (k + 0) * H))[cx];
            float4 b1 = ((float4*)(Ws + (k + 1) * H))[cx];
            float4 b2 = ((float4*)(Ws + (k + 2) * H))[cx];
            float4 b3 = ((float4*)(Ws + (k + 3) * H))[cx];
#pragma unroll
            for (int r = 0; r < 8; r++) {
                float4 av = *(float4*)(As + (8 * mg + r) * H + kc + k);
                acc[r][0] += av.x * b0.x + av.y * b1.x + av.z * b2.x + av.w * b3.x;
                acc[r][1] += av.x * b0.y + av.y * b1.y + av.z * b2.y + av.w * b3.y;
                acc[r][2] += av.x * b0.z + av.y * b1.z + av.z * b2.z + av.w * b3.z;
                acc[r][3] += av.x * b0.w + av.y * b1.w + av.z * b2.w + av.w * b3.w;
            }
        }
    }

    float4 bv = make_float4(0.f, 0.f, 0.f, 0.f);
    if (bias) bv = ((const float4*)bias)[cx];
#pragma unroll
    for (int r = 0; r < 8; r++) {
        int n = n0 + 8 * mg + r;
        if (n >= NN) break;
        float4 v;
        v.x = acc[r][0] + bv.x; v.y = acc[r][1] + bv.y;
        v.z = acc[r][2] + bv.z; v.w = acc[r][3] + bv.w;
        if (act) { v.x = ssp(v.x); v.y = ssp(v.y); v.z = ssp(v.z); v.w = ssp(v.w); }
        float4* op = (float4*)(out + (size_t)n * H) + cx;
        if (residual) {
            float4 o = *op;
            v.x += o.x; v.y += o.y; v.z += o.z; v.w += o.w;
        }
        *op = v;
    }
}

// -------- small GEMM for head (kin=128, kout=64) --------
__global__ void node_gemm_kernel(const float* __restrict__ in, const float* __restrict__ W,
                                 const float* __restrict__ bias, float* __restrict__ out,
                                 int kin, int kout, int act) {
    __shared__ float As[16 * H];
    int n0 = blockIdx.x * 16;
    for (int i = threadIdx.x; i < 16 * kin; i += blockDim.x)
        As[i] = in[n0 * kin + i];
    __syncthreads();
    int j = threadIdx.x;
    if (j < kout) {
        float acc[16];
#pragma unroll
        for (int m = 0; m < 16; m++) acc[m] = 0.0f;
        for (int k = 0; k < kin; k++) {
            float wv = W[k * kout + j];
#pragma unroll
            for (int m = 0; m < 16; m++) acc[m] += wv * As[m * kin + k];
        }
        float b = bias ? bias[j] : 0.0f;
#pragma unroll
        for (int m = 0; m < 16; m++) {
            float v = acc[m] + b;
            if (act) v = ssp(v);
            out[(n0 + m) * kout + j] = v;
        }
    }
}

// -------- edge message + scatter: one warp per edge, v4 vector RED --------
__global__ void edge_msg_kernel(const int* __restrict__ ei) {
    int e = (blockIdx.x * blockDim.x + threadIdx.x) >> 5;
    int lane = threadIdx.x & 31;
    if (e >= NE) return;
    float w = g_w[e];
    if (w >= WMAX) return;  // Wf exactly 0 (gaussians underflow, zero biases)
    float f = w * ((float)(TABN - 1) / WMAX);
    int i0 = (int)f;
    if (i0 > TABN - 2) i0 = TABN - 2;
    float fr = f - (float)i0;
    int s = ei[e], d = ei[NE + e];

    const float4* ta = (const float4*)(g_tab + i0 * H);
    const float4* tb = (const float4*)(g_tab + (i0 + 1) * H);
    const float4* hx = (const float4*)(g_hx + (size_t)s * H);
    float* ag = g_agg + (size_t)d * H + lane * 4;

    float4 a = ta[lane];
    float4 b = tb[lane];
    float4 hv = hx[lane];
    float m0 = hv.x * fmaf(fr, b.x - a.x, a.x);
    float m1 = hv.y * fmaf(fr, b.y - a.y, a.y);
    float m2 = hv.z * fmaf(fr, b.z - a.z, a.z);
    float m3 = hv.w * fmaf(fr, b.w - a.w, a.w);
    asm volatile("red.global.add.v4.f32 [%0], {%1, %2, %3, %4};"
                 :: "l"(ag), "f"(m0), "f"(m1), "f"(m2), "f"(m3)
                 : "memory");
}

// -------- head stage 2 + per-graph reduction --------
__global__ void head2_kernel(const float* __restrict__ w2, const float* __restrict__ b2,
                             const int* __restrict__ batch) {
    int n = (blockIdx.x * blockDim.x + threadIdx.x) >> 5;
    int lane = threadIdx.x & 31;
    if (n >= NN) return;
    float v = g_agg[n * 64 + lane] * w2[lane] + g_agg[n * 64 + 32 + lane] * w2[32 + lane];
#pragma unroll
    for (int o = 16; o > 0; o >>= 1) v += __shfl_down_sync(0xffffffffu, v, o);
    if (lane == 0) {
        int g = batch[n];
        atomicAdd(&g_gsum[g], v + b2[0]);
        atomicAdd(&g_gcnt[g], 1.0f);
    }
}

__global__ void finalize_kernel(float* __restrict__ out) {
    int g = threadIdx.x;
    if (g < NGR) out[g] = g_gsum[g] / fmaxf(g_gcnt[g], 1.0f);
}

extern "C" void kernel_launch(void* const* d_in, const int* in_sizes, int n_in,
                              void* d_out, int out_size) {
    const float* pos     = (const float*)d_in[0];
    const float* shift   = (const float*)d_in[1];
    const float* emb     = (const float*)d_in[2];
    const float* mlp_w1  = (const float*)d_in[3];
    const float* mlp_b1  = (const float*)d_in[4];
    const float* mlp_w2  = (const float*)d_in[5];
    const float* mlp_b2  = (const float*)d_in[6];
    const float* cf_w1   = (const float*)d_in[7];
    const float* cf_w2   = (const float*)d_in[8];
    const float* cf_b2   = (const float*)d_in[9];
    const float* lin_w   = (const float*)d_in[10];
    const float* lin_b   = (const float*)d_in[11];
    const float* head_w1 = (const float*)d_in[12];
    const float* head_b1 = (const float*)d_in[13];
    const float* head_w2 = (const float*)d_in[14];
    const float* head_b2 = (const float*)d_in[15];
    const int*   z       = (const int*)d_in[16];
    const int*   ei      = (const int*)d_in[17];
    const int*   batch   = (const int*)d_in[18];
    float* out = (float*)d_out;

    float *p_h, *p_hx, *p_agg;
    cudaGetSymbolAddress((void**)&p_h,   g_h);
    cudaGetSymbolAddress((void**)&p_hx,  g_hx);
    cudaGetSymbolAddress((void**)&p_agg, g_agg);

    const int gemm_blocks = (NN + GM - 1) / GM;

    edge_w_kernel<<<(NE + 255) / 256, 256>>>(pos, shift, ei);
    embed_kernel<<<(NN * H + 255) / 256, 256>>>(emb, z);
    zero_small_kernel<<<1, 128>>>();

    for (int i = 0; i < 3; i++) {
        table_kernel<<<TABN / 8, 128>>>(mlp_w1 + i * NG * H, mlp_b1 + i * H,
                                        mlp_w2 + i * H * H,  mlp_b2 + i * H);
        zero_agg_kernel<<<(NN * H + 255) / 256, 256>>>();
        // hx = h @ cf_w1[i]
        gemm128_kernel<<<gemm_blocks, 256>>>(p_h, cf_w1 + i * H * H, nullptr, p_hx, 0, 0);
        // agg[dst] += hx[src] * Wf(w)*C(w)
        edge_msg_kernel<<<NE / 8, 256>>>(ei);
        // t = ssp(agg @ cf_w2 + b2)
        gemm128_kernel<<<gemm_blocks, 256>>>(p_agg, cf_w2 + i * H * H, cf_b2 + i * H, p_hx, 1, 0);
        // h += t @ lin_w + lin_b
        gemm128_kernel<<<gemm_blocks, 256>>>(p_hx, lin_w + i * H * H, lin_b + i * H, p_h, 0, 1);
    }

    // head: u = ssp(h @ head_w1 + b1) -> g_agg reused as [N,64]
    node_gemm_kernel<<<(NN + 15) / 16, 128>>>(p_h, head_w1, head_b1, p_agg, H, 64, 1);
    head2_kernel<<<(NN * 32 + 255) / 256, 256>>>(head_w2, head_b2, batch);
    finalize_kernel<<<1, 128>>>(out);
}

// round 4
// speedup vs baseline: 2.1903x; 1.3871x over previous
#include <cuda_runtime.h>
#include <cuda_fp16.h>
#include <math.h>

#define NN 50000
#define NE 1600000
#define H 128
#define NG 50
#define NGR 128
#define TABN 8192
#define WMAX 9.6f
#define GM 64   // gemm M-tile
#define KC 32   // gemm K-chunk staged in smem

// -------- scratch (device globals: allocation-free) --------
__device__ float g_h[NN * H];     // node features
__device__ float g_hx[NN * H];    // h @ cf_w1 (also reused as t buffer)
__device__ float g_agg[NN * H];   // gather output (also reused [N,64] for head)
__device__ float g_w[NE];         // edge distances
__device__ float g_tab[TABN * H]; // Wf(w)*C(w) lookup table (per interaction)
__device__ float g_gsum[NGR];
__device__ float g_gcnt[NGR];
// CSR for dst-grouped active edges
__device__ int   g_cnt[NN];
__device__ int   g_off[NN + 1];
__device__ int   g_cur[NN];
__device__ uint2 g_edges[NE];     // {src, (i0<<16)|half(fr)}

__device__ __forceinline__ float ssp(float x) {
    return fmaxf(x, 0.0f) + log1pf(expf(-fabsf(x))) - 0.69314718055994531f;
}

// -------- edge geometry --------
__global__ void edge_w_kernel(const float* __restrict__ pos,
                              const float* __restrict__ shift,
                              const int* __restrict__ ei) {
    int e = blockIdx.x * blockDim.x + threadIdx.x;
    if (e >= NE) return;
    int s = ei[e], d = ei[NE + e];
    float dx = pos[s * 3 + 0] - pos[d * 3 + 0] - shift[e * 3 + 0];
    float dy = pos[s * 3 + 1] - pos[d * 3 + 1] - shift[e * 3 + 1];
    float dz = pos[s * 3 + 2] - pos[d * 3 + 2] - shift[e * 3 + 2];
    g_w[e] = sqrtf(dx * dx + dy * dy + dz * dz);
}

// -------- h = emb[z] --------
__global__ void embed_kernel(const float* __restrict__ emb, const int* __restrict__ z) {
    int i = blockIdx.x * blockDim.x + threadIdx.x;
    if (i >= NN * H) return;
    int n = i >> 7, c = i & 127;
    g_h[i] = emb[z[n] * H + c];
}

__global__ void zero_misc_kernel() {
    int i = blockIdx.x * blockDim.x + threadIdx.x;
    if (i < NN) g_cnt[i] = 0;
    if (i < NGR) { g_gsum[i] = 0.0f; g_gcnt[i] = 0.0f; }
}

// -------- CSR build: histogram of active-edge dst --------
__global__ void hist_kernel(const int* __restrict__ ei) {
    int e = blockIdx.x * blockDim.x + threadIdx.x;
    if (e >= NE) return;
    if (g_w[e] < WMAX) atomicAdd(&g_cnt[ei[NE + e]], 1);
}

// -------- single-block exclusive scan of g_cnt -> g_off, copy to g_cur --------
__global__ void scan_kernel() {
    __shared__ int warp_sums[32];
    __shared__ int s_carry;
    int tid = threadIdx.x;
    int lane = tid & 31, wid = tid >> 5;
    if (tid == 0) { s_carry = 0; g_off[0] = 0; }
    __syncthreads();
    for (int base = 0; base < NN; base += 1024) {
        int i = base + tid;
        int v = (i < NN) ? g_cnt[i] : 0;
        int x = v;
#pragma unroll
        for (int o = 1; o < 32; o <<= 1) {
            int y = __shfl_up_sync(0xffffffffu, x, o);
            if (lane >= o) x += y;
        }
        if (lane == 31) warp_sums[wid] = x;
        __syncthreads();
        if (wid == 0) {
            int ws = warp_sums[lane];
#pragma unroll
            for (int o = 1; o < 32; o <<= 1) {
                int y = __shfl_up_sync(0xffffffffu, ws, o);
                if (lane >= o) ws += y;
            }
            warp_sums[lane] = ws;
        }
        __syncthreads();
        int incl = x + (wid > 0 ? warp_sums[wid - 1] : 0);
        int total = warp_sums[31];
        int carry = s_carry;
        if (i < NN) {
            g_off[i + 1] = carry + incl;
            g_cur[i] = carry + incl - v;   // exclusive = start cursor
        }
        __syncthreads();
        if (tid == 0) s_carry = carry + total;
        __syncthreads();
    }
}

// -------- fill CSR with packed edge records --------
__global__ void fill_kernel(const int* __restrict__ ei) {
    int e = blockIdx.x * blockDim.x + threadIdx.x;
    if (e >= NE) return;
    float w = g_w[e];
    if (w >= WMAX) return;
    int d = ei[NE + e];
    int pos = atomicAdd(&g_cur[d], 1);
    float f = w * ((float)(TABN - 1) / WMAX);
    int i0 = (int)f;
    if (i0 > TABN - 2) i0 = TABN - 2;
    float fr = f - (float)i0;
    unsigned short hb = __half_as_ushort(__float2half_rn(fr));
    g_edges[pos] = make_uint2((unsigned)ei[e], ((unsigned)i0 << 16) | hb);
}

// -------- build Wf(w)*C(w) lookup table: 8 samples per block --------
__global__ void table_kernel(const float* __restrict__ w1, const float* __restrict__ b1,
                             const float* __restrict__ w2, const float* __restrict__ b2) {
    __shared__ float gs[8][NG];
    __shared__ float t1s[8][H];
    int s0 = blockIdx.x * 8;
    int j = threadIdx.x;
    const float step = WMAX / (float)(TABN - 1);
    const float spacing = 8.0f / 49.0f;
    const float coeff = -0.5f / (spacing * spacing);

    for (int idx = j; idx < 8 * NG; idx += blockDim.x) {
        int m = idx / NG, k = idx - m * NG;
        float ws = (float)(s0 + m) * step;
        float dd = ws - (float)k * spacing;
        gs[m][k] = expf(coeff * dd * dd);
    }
    __syncthreads();

    float acc[8];
#pragma unroll
    for (int m = 0; m < 8; m++) acc[m] = 0.0f;
    for (int k = 0; k < NG; k++) {
        float wv = w1[k * H + j];
#pragma unroll
        for (int m = 0; m < 8; m++) acc[m] += wv * gs[m][k];
    }
    float bb = b1[j];
#pragma unroll
    for (int m = 0; m < 8; m++) t1s[m][j] = ssp(acc[m] + bb);
    __syncthreads();

#pragma unroll
    for (int m = 0; m < 8; m++) acc[m] = 0.0f;
    for (int k = 0; k < H; k++) {
        float wv = w2[k * H + j];
#pragma unroll
        for (int m = 0; m < 8; m++) acc[m] += wv * t1s[m][k];
    }
    float b2v = b2[j];
#pragma unroll
    for (int m = 0; m < 8; m++) {
        float ws = (float)(s0 + m) * step;
        float C = 0.5f * (cosf(ws * (3.14159265358979f / 8.0f)) + 1.0f);
        g_tab[(s0 + m) * H + j] = (acc[m] + b2v) * C;
    }
}

// -------- tiled node GEMM: out = [ssp](in @ W + b) [+= residual] --------
__global__ __launch_bounds__(256) void gemm128_kernel(
    const float* __restrict__ in, const float* __restrict__ W,
    const float* __restrict__ bias, float* __restrict__ out,
    int act, int residual) {
    __shared__ float As[GM * H];   // 32 KB
    __shared__ float Ws[KC * H];   // 16 KB
    int n0 = blockIdx.x * GM;
    int tid = threadIdx.x;

    float4* As4 = (float4*)As;
    for (int i = tid; i < GM * H / 4; i += 256) {
        int m = i >> 5;
        float4 v = make_float4(0.f, 0.f, 0.f, 0.f);
        if (n0 + m < NN) v = ((const float4*)(in + (size_t)(n0 + m) * H))[i & 31];
        As4[i] = v;
    }

    int cx = tid & 31;
    int mg = tid >> 5;
    float acc[8][4];
#pragma unroll
    for (int r = 0; r < 8; r++)
#pragma unroll
        for (int c = 0; c < 4; c++) acc[r][c] = 0.0f;

    for (int kc = 0; kc < H; kc += KC) {
        __syncthreads();
        const float4* Wc4 = (const float4*)(W + kc * H);
        float4* Ws4 = (float4*)Ws;
#pragma unroll
        for (int i = 0; i < KC * H / 4 / 256; i++)
            Ws4[tid + i * 256] = Wc4[tid + i * 256];
        __syncthreads();

#pragma unroll
        for (int k = 0; k < KC; k += 4) {
            float4 b0 = ((float4*)(Ws + (k + 0) * H))[cx];
            float4 b1 = ((float4*)(Ws + (k + 1) * H))[cx];
            float4 b2 = ((float4*)(Ws + (k + 2) * H))[cx];
            float4 b3 = ((float4*)(Ws + (k + 3) * H))[cx];
#pragma unroll
            for (int r = 0; r < 8; r++) {
                float4 av = *(float4*)(As + (8 * mg + r) * H + kc + k);
                acc[r][0] += av.x * b0.x + av.y * b1.x + av.z * b2.x + av.w * b3.x;
                acc[r][1] += av.x * b0.y + av.y * b1.y + av.z * b2.y + av.w * b3.y;
                acc[r][2] += av.x * b0.z + av.y * b1.z + av.z * b2.z + av.w * b3.z;
                acc[r][3] += av.x * b0.w + av.y * b1.w + av.z * b2.w + av.w * b3.w;
            }
        }
    }

    float4 bv = make_float4(0.f, 0.f, 0.f, 0.f);
    if (bias) bv = ((const float4*)bias)[cx];
#pragma unroll
    for (int r = 0; r < 8; r++) {
        int n = n0 + 8 * mg + r;
        if (n >= NN) break;
        float4 v;
        v.x = acc[r][0] + bv.x; v.y = acc[r][1] + bv.y;
        v.z = acc[r][2] + bv.z; v.w = acc[r][3] + bv.w;
        if (act) { v.x = ssp(v.x); v.y = ssp(v.y); v.z = ssp(v.z); v.w = ssp(v.w); }
        float4* op = (float4*)(out + (size_t)n * H) + cx;
        if (residual) {
            float4 o = *op;
            v.x += o.x; v.y += o.y; v.z += o.z; v.w += o.w;
        }
        *op = v;
    }
}

// -------- small GEMM for head (kin=128, kout=64) --------
__global__ void node_gemm_kernel(const float* __restrict__ in, const float* __restrict__ W,
                                 const float* __restrict__ bias, float* __restrict__ out,
                                 int kin, int kout, int act) {
    __shared__ float As[16 * H];
    int n0 = blockIdx.x * 16;
    for (int i = threadIdx.x; i < 16 * kin; i += blockDim.x)
        As[i] = in[n0 * kin + i];
    __syncthreads();
    int j = threadIdx.x;
    if (j < kout) {
        float acc[16];
#pragma unroll
        for (int m = 0; m < 16; m++) acc[m] = 0.0f;
        for (int k = 0; k < kin; k++) {
            float wv = W[k * kout + j];
#pragma unroll
            for (int m = 0; m < 16; m++) acc[m] += wv * As[m * kin + k];
        }
        float b = bias ? bias[j] : 0.0f;
#pragma unroll
        for (int m = 0; m < 16; m++) {
            float v = acc[m] + b;
            if (act) v = ssp(v);
            out[(n0 + m) * kout + j] = v;
        }
    }
}

// -------- gather: one warp per dst node, register accumulation, no atomics --------
__global__ __launch_bounds__(256) void gather_kernel() {
    int n = (blockIdx.x * blockDim.x + threadIdx.x) >> 5;
    int lane = threadIdx.x & 31;
    if (n >= NN) return;
    int p = g_off[n], end = g_off[n + 1];
    float4 acc = make_float4(0.f, 0.f, 0.f, 0.f);

    for (; p + 2 <= end; p += 2) {
        uint2 e0 = g_edges[p];
        uint2 e1 = g_edges[p + 1];
        int i00 = e0.y >> 16, i01 = e1.y >> 16;
        float fr0 = __half2float(__ushort_as_half((unsigned short)(e0.y & 0xffffu)));
        float fr1 = __half2float(__ushort_as_half((unsigned short)(e1.y & 0xffffu)));
        float4 a0 = ((const float4*)(g_tab + (size_t)i00 * H))[lane];
        float4 b0 = ((const float4*)(g_tab + (size_t)i00 * H + H))[lane];
        float4 h0 = ((const float4*)(g_hx + (size_t)e0.x * H))[lane];
        float4 a1 = ((const float4*)(g_tab + (size_t)i01 * H))[lane];
        float4 b1 = ((const float4*)(g_tab + (size_t)i01 * H + H))[lane];
        float4 h1 = ((const float4*)(g_hx + (size_t)e1.x * H))[lane];
        acc.x += h0.x * fmaf(fr0, b0.x - a0.x, a0.x) + h1.x * fmaf(fr1, b1.x - a1.x, a1.x);
        acc.y += h0.y * fmaf(fr0, b0.y - a0.y, a0.y) + h1.y * fmaf(fr1, b1.y - a1.y, a1.y);
        acc.z += h0.z * fmaf(fr0, b0.z - a0.z, a0.z) + h1.z * fmaf(fr1, b1.z - a1.z, a1.z);
        acc.w += h0.w * fmaf(fr0, b0.w - a0.w, a0.w) + h1.w * fmaf(fr1, b1.w - a1.w, a1.w);
    }
    if (p < end) {
        uint2 e0 = g_edges[p];
        int i00 = e0.y >> 16;
        float fr0 = __half2float(__ushort_as_half((unsigned short)(e0.y & 0xffffu)));
        float4 a0 = ((const float4*)(g_tab + (size_t)i00 * H))[lane];
        float4 b0 = ((const float4*)(g_tab + (size_t)i00 * H + H))[lane];
        float4 h0 = ((const float4*)(g_hx + (size_t)e0.x * H))[lane];
        acc.x += h0.x * fmaf(fr0, b0.x - a0.x, a0.x);
        acc.y += h0.y * fmaf(fr0, b0.y - a0.y, a0.y);
        acc.z += h0.z * fmaf(fr0, b0.z - a0.z, a0.z);
        acc.w += h0.w * fmaf(fr0, b0.w - a0.w, a0.w);
    }
    ((float4*)(g_agg + (size_t)n * H))[lane] = acc;
}

// -------- head stage 2 + per-graph reduction --------
__global__ void head2_kernel(const float* __restrict__ w2, const float* __restrict__ b2,
                             const int* __restrict__ batch) {
    int n = (blockIdx.x * blockDim.x + threadIdx.x) >> 5;
    int lane = threadIdx.x & 31;
    if (n >= NN) return;
    float v = g_agg[n * 64 + lane] * w2[lane] + g_agg[n * 64 + 32 + lane] * w2[32 + lane];
#pragma unroll
    for (int o = 16; o > 0; o >>= 1) v += __shfl_down_sync(0xffffffffu, v, o);
    if (lane == 0) {
        int g = batch[n];
        atomicAdd(&g_gsum[g], v + b2[0]);
        atomicAdd(&g_gcnt[g], 1.0f);
    }
}

__global__ void finalize_kernel(float* __restrict__ out) {
    int g = threadIdx.x;
    if (g < NGR) out[g] = g_gsum[g] / fmaxf(g_gcnt[g], 1.0f);
}

extern "C" void kernel_launch(void* const* d_in, const int* in_sizes, int n_in,
                              void* d_out, int out_size) {
    const float* pos     = (const float*)d_in[0];
    const float* shift   = (const float*)d_in[1];
    const float* emb     = (const float*)d_in[2];
    const float* mlp_w1  = (const float*)d_in[3];
    const float* mlp_b1  = (const float*)d_in[4];
    const float* mlp_w2  = (const float*)d_in[5];
    const float* mlp_b2  = (const float*)d_in[6];
    const float* cf_w1   = (const float*)d_in[7];
    const float* cf_w2   = (const float*)d_in[8];
    const float* cf_b2   = (const float*)d_in[9];
    const float* lin_w   = (const float*)d_in[10];
    const float* lin_b   = (const float*)d_in[11];
    const float* head_w1 = (const float*)d_in[12];
    const float* head_b1 = (const float*)d_in[13];
    const float* head_w2 = (const float*)d_in[14];
    const float* head_b2 = (const float*)d_in[15];
    const int*   z       = (const int*)d_in[16];
    const int*   ei      = (const int*)d_in[17];
    const int*   batch   = (const int*)d_in[18];
    float* out = (float*)d_out;

    float *p_h, *p_hx, *p_agg;
    cudaGetSymbolAddress((void**)&p_h,   g_h);
    cudaGetSymbolAddress((void**)&p_hx,  g_hx);
    cudaGetSymbolAddress((void**)&p_agg, g_agg);

    const int gemm_blocks = (NN + GM - 1) / GM;

    edge_w_kernel<<<(NE + 255) / 256, 256>>>(pos, shift, ei);
    embed_kernel<<<(NN * H + 255) / 256, 256>>>(emb, z);
    zero_misc_kernel<<<(NN + 255) / 256, 256>>>();
    hist_kernel<<<(NE + 255) / 256, 256>>>(ei);
    scan_kernel<<<1, 1024>>>();
    fill_kernel<<<(NE + 255) / 256, 256>>>(ei);

    for (int i = 0; i < 3; i++) {
        table_kernel<<<TABN / 8, 128>>>(mlp_w1 + i * NG * H, mlp_b1 + i * H,
                                        mlp_w2 + i * H * H,  mlp_b2 + i * H);
        // hx = h @ cf_w1[i]
        gemm128_kernel<<<gemm_blocks, 256>>>(p_h, cf_w1 + i * H * H, nullptr, p_hx, 0, 0);
        // agg[n] = sum_{e: dst=n} hx[src] * Wf(w)*C(w)   (gather, no atomics)
        gather_kernel<<<(NN * 32 + 255) / 256, 256>>>();
        // t = ssp(agg @ cf_w2 + b2)
        gemm128_kernel<<<gemm_blocks, 256>>>(p_agg, cf_w2 + i * H * H, cf_b2 + i * H, p_hx, 1, 0);
        // h += t @ lin_w + lin_b
        gemm128_kernel<<<gemm_blocks, 256>>>(p_hx, lin_w + i * H * H, lin_b + i * H, p_h, 0, 1);
    }

    // head: u = ssp(h @ head_w1 + b1) -> g_agg reused as [N,64]
    node_gemm_kernel<<<(NN + 15) / 16, 128>>>(p_h, head_w1, head_b1, p_agg, H, 64, 1);
    head2_kernel<<<(NN * 32 + 255) / 256, 256>>>(head_w2, head_b2, batch);
    finalize_kernel<<<1, 128>>>(out);
}